// round 8
// baseline (speedup 1.0000x reference)
#include <cuda_runtime.h>
#include <cuda_bf16.h>

#define NMAX 50000
#define EMAX 800000
#define F 128
#define EFD 6

#define PREP_BLOCKS 592
#define PREP_T 512

// ---- packed dual-fp32 ops (Blackwell f32x2) --------------------------------
#define PACK_F32X2(d, a, b) \
    asm("mov.b64 %0, {%1, %2};" : "=l"(d) : "f"(a), "f"(b))
#define FMA_F32X2(d, a, b, c) \
    asm("fma.rn.f32x2 %0, %1, %2, %3;" : "=l"(d) : "l"(a), "l"(b), "l"(c))
#define UNPACK_F32X2(lo, hi, v) \
    asm("mov.b64 {%0, %1}, %2;" : "=f"(lo), "=f"(hi) : "l"(v))

// ---------------- device scratch ----------------
__device__ int    g_is64;
__device__ int    g_counts[NMAX];
__device__ int    g_cursor[NMAX];
__device__ int    g_rowptr[NMAX + 1];
__device__ int    g_src[EMAX];
__device__ int    g_dst[EMAX];
__device__ int2   g_edges[EMAX];
__device__ float4 g_aggX[NMAX * (F / 4)];
__device__ float  g_aggE[NMAX * EFD];
__device__ int    g_blocksum[256];
__device__ int    g_blockoff[256];
__device__ int    g_bar[5];

// ---------------- software grid barrier -------------------------------------
__device__ __forceinline__ void grid_barrier(int id) {
    __syncthreads();
    if (threadIdx.x == 0) {
        __threadfence();
        atomicAdd(&g_bar[id], 1);
        const volatile int* vb = g_bar;
        while (vb[id] < PREP_BLOCKS) { }
        __threadfence();
    }
    __syncthreads();
}

// ---------------- fused prep: zero+detect | hist | scan | scatter ------------
__global__ void __launch_bounds__(PREP_T, 4)
k_prep(const void* __restrict__ ei, int N, int E) {
    const int tid  = blockIdx.x * PREP_T + threadIdx.x;
    const int nth  = PREP_BLOCKS * PREP_T;
    const int lane = threadIdx.x & 31;
    const int T    = (N + 255) >> 8;

    if (blockIdx.x == 0 && threadIdx.x == 0) {
        const long long* p = (const long long*)ei;
        int ok = 1;
        int lim = E < 128 ? E : 128;
        for (int j = 0; j < lim; j++) {
            long long v = p[j];
            if (v < 0 || v >= (long long)N) { ok = 0; break; }
        }
        g_is64 = ok;
        atomicExch(&g_bar[4], 0);
    }
    for (int i = tid; i < N; i += nth) g_counts[i] = 0;
    grid_barrier(0);

    const int is64 = __ldcg(&g_is64);
    if (is64) {
        const longlong2* p = (const longlong2*)ei;
        for (int e = tid; e < E; e += nth) {
            longlong2 v = p[e];
            int s = (int)v.x, d = (int)v.y;
            g_src[e] = s; g_dst[e] = d;
            atomicAdd(&g_counts[d], 1);
        }
    } else {
        const int2* p = (const int2*)ei;
        for (int e = tid; e < E; e += nth) {
            int2 v = p[e];
            g_src[e] = v.x; g_dst[e] = v.y;
            atomicAdd(&g_counts[v.y], 1);
        }
    }
    grid_barrier(1);
    if (blockIdx.x == 0 && threadIdx.x == 0) atomicExch(&g_bar[0], 0);

    {
        int gw = tid >> 5;
        int nw = nth >> 5;
        for (int t = gw; t < T; t += nw) {
            int base = t << 8;
            int v[8]; int s = 0;
            #pragma unroll
            for (int j = 0; j < 8; j++) {
                int idx = base + lane * 8 + j;
                int c = (idx < N) ? __ldcg(&g_counts[idx]) : 0;
                v[j] = s; s += c;
            }
            int x = s;
            #pragma unroll
            for (int o = 1; o < 32; o <<= 1) {
                int y = __shfl_up_sync(0xffffffffu, x, o);
                if (lane >= o) x += y;
            }
            int excl = x - s;
            #pragma unroll
            for (int j = 0; j < 8; j++) {
                int idx = base + lane * 8 + j;
                if (idx < N) g_rowptr[idx] = excl + v[j];
            }
            if (lane == 31) g_blocksum[t] = x;
        }
    }
    grid_barrier(2);
    if (blockIdx.x == 0 && threadIdx.x == 0) atomicExch(&g_bar[1], 0);

    if (blockIdx.x == 0 && threadIdx.x < 32) {
        int vals[7]; int s = 0;
        #pragma unroll
        for (int j = 0; j < 7; j++) {
            int idx = lane * 7 + j;
            int v = (idx < T) ? __ldcg(&g_blocksum[idx]) : 0;
            vals[j] = s; s += v;
        }
        int x = s;
        #pragma unroll
        for (int o = 1; o < 32; o <<= 1) {
            int y = __shfl_up_sync(0xffffffffu, x, o);
            if (lane >= o) x += y;
        }
        int excl = x - s;
        #pragma unroll
        for (int j = 0; j < 7; j++) {
            int idx = lane * 7 + j;
            if (idx < T) g_blockoff[idx] = excl + vals[j];
        }
        if (lane == 31) g_rowptr[N] = x;
    }
    grid_barrier(3);
    if (blockIdx.x == 0 && threadIdx.x == 0) atomicExch(&g_bar[2], 0);

    for (int i = tid; i < N; i += nth) {
        int r = __ldcg(&g_rowptr[i]) + __ldcg(&g_blockoff[i >> 8]);
        g_rowptr[i] = r;
        g_cursor[i] = r;
    }
    grid_barrier(4);
    if (blockIdx.x == 0 && threadIdx.x == 0) atomicExch(&g_bar[3], 0);

    for (int e0 = tid * 4; e0 < E; e0 += nth * 4) {
        int d[4], s[4];
        #pragma unroll
        for (int j = 0; j < 4; j++) {
            int e = e0 + j;
            if (e < E) { d[j] = __ldcg(&g_dst[e]); s[j] = __ldcg(&g_src[e]); }
        }
        #pragma unroll
        for (int j = 0; j < 4; j++) {
            int e = e0 + j;
            if (e < E) {
                int p = atomicAdd(&g_cursor[d[j]], 1);
                g_edges[p] = make_int2(s[j], e);
            }
        }
    }
}

// ---------------- K4: warp-per-node aggregation (round-2 style) -------------
__global__ void __launch_bounds__(256)
k4_aggregate(const float4* __restrict__ X4, const float* __restrict__ eF,
             int N) {
    int gwarp = (blockIdx.x * blockDim.x + threadIdx.x) >> 5;
    int lane  = threadIdx.x & 31;
    if (gwarp >= N) return;
    int v = gwarp;
    int s0 = g_rowptr[v], s1 = g_rowptr[v + 1];
    float4 acc = make_float4(0.f, 0.f, 0.f, 0.f);
    float ae = 0.f;
    for (int base = s0; base < s1; base += 32) {
        int cnt = s1 - base; if (cnt > 32) cnt = 32;
        int2 se = __ldcg(&g_edges[base + (lane < cnt ? lane : 0)]);
        for (int j = 0; j < cnt; j += 8) {
            #pragma unroll
            for (int u = 0; u < 8; u++) {
                if (j + u < cnt) {  // uniform across warp
                    int sj = __shfl_sync(0xffffffffu, se.x, j + u);
                    int ej = __shfl_sync(0xffffffffu, se.y, j + u);
                    float4 xv = __ldcg(&X4[(long)sj * 32 + lane]);
                    acc.x += xv.x; acc.y += xv.y;
                    acc.z += xv.z; acc.w += xv.w;
                    if (lane < EFD) ae += __ldcg(&eF[(long)ej * EFD + lane]);
                }
            }
        }
    }
    g_aggX[(long)v * 32 + lane] = acc;
    if (lane < EFD) g_aggE[v * EFD + lane] = ae;
}

// ---------------- K5: f32x2 GEMM + edge GEMM + bias*deg + relu --------------
#define K5T 256
#define K5W 8                 // warps/block
#define FRPW 8                // rows/warp
#define K5_SMEM (K5W * FRPW * 64 * 16)   // dup-pair staging: 64 KB

__global__ void __launch_bounds__(K5T)
k5_final(const float4* __restrict__ W4, const float4* __restrict__ b4p,
         const float4* __restrict__ We4, const float4* __restrict__ be4,
         float4* __restrict__ out4, int N) {
    extern __shared__ float4 xsd[];     // [K5W][FRPW*64]
    int tid = threadIdx.x, warp = tid >> 5, lane = tid & 31;
    float4* xw = xsd + warp * (FRPW * 64);

    int row0 = (blockIdx.x * K5W + warp) * FRPW;
    if (row0 >= N) return;

    // ---- stage 8 rows as duplicated pairs (x,x,y,y)(z,z,w,w)
    #pragma unroll
    for (int r = 0; r < FRPW; r++) {
        int row = row0 + r;
        float4 a = (row < N) ? __ldcg(&g_aggX[(long)row * 32 + lane])
                             : make_float4(0.f, 0.f, 0.f, 0.f);
        xw[r * 64 + 2 * lane]     = make_float4(a.x, a.x, a.y, a.y);
        xw[r * 64 + 2 * lane + 1] = make_float4(a.z, a.z, a.w, a.w);
    }
    __syncwarp();

    // ---- GEMM: f32x2, W via L1, x via broadcast LDS of dup pairs
    unsigned long long a01[FRPW], a23[FRPW];
    #pragma unroll
    for (int r = 0; r < FRPW; r++) { a01[r] = 0ULL; a23[r] = 0ULL; }

    for (int kb = 0; kb < F; kb += 4) {
        unsigned long long w01[4], w23[4];
        #pragma unroll
        for (int kk = 0; kk < 4; kk++) {
            float4 w4 = __ldg(&W4[(kb + kk) * 32 + lane]);
            PACK_F32X2(w01[kk], w4.x, w4.y);
            PACK_F32X2(w23[kk], w4.z, w4.w);
        }
        #pragma unroll
        for (int r = 0; r < FRPW; r++) {
            ulonglong2 xa = *(const ulonglong2*)&xw[r * 64 + (kb >> 1)];
            ulonglong2 xb = *(const ulonglong2*)&xw[r * 64 + (kb >> 1) + 1];
            FMA_F32X2(a01[r], xa.x, w01[0], a01[r]);
            FMA_F32X2(a23[r], xa.x, w23[0], a23[r]);
            FMA_F32X2(a01[r], xa.y, w01[1], a01[r]);
            FMA_F32X2(a23[r], xa.y, w23[1], a23[r]);
            FMA_F32X2(a01[r], xb.x, w01[2], a01[r]);
            FMA_F32X2(a23[r], xb.x, w23[2], a23[r]);
            FMA_F32X2(a01[r], xb.y, w01[3], a01[r]);
            FMA_F32X2(a23[r], xb.y, w23[3], a23[r]);
        }
    }

    // ---- epilogue
    float4 bb = __ldg(&b4p[lane]);
    float4 be = __ldg(&be4[lane]);
    float4 bs = make_float4(bb.x + be.x, bb.y + be.y, bb.z + be.z, bb.w + be.w);
    #pragma unroll
    for (int r = 0; r < FRPW; r++) {
        int row = row0 + r;
        if (row >= N) break;
        float deg = (float)(__ldcg(&g_rowptr[row + 1]) - __ldcg(&g_rowptr[row]));
        float4 o;
        UNPACK_F32X2(o.x, o.y, a01[r]);
        UNPACK_F32X2(o.z, o.w, a23[r]);
        o.x = fmaf(deg, bs.x, o.x);
        o.y = fmaf(deg, bs.y, o.y);
        o.z = fmaf(deg, bs.z, o.z);
        o.w = fmaf(deg, bs.w, o.w);
        #pragma unroll
        for (int k = 0; k < EFD; k++) {
            float ek = __ldcg(&g_aggE[row * EFD + k]);   // warp-uniform load
            float4 w4 = __ldg(&We4[k * 32 + lane]);
            o.x = fmaf(ek, w4.x, o.x);
            o.y = fmaf(ek, w4.y, o.y);
            o.z = fmaf(ek, w4.z, o.z);
            o.w = fmaf(ek, w4.w, o.w);
        }
        o.x = fmaxf(o.x, 0.f); o.y = fmaxf(o.y, 0.f);
        o.z = fmaxf(o.z, 0.f); o.w = fmaxf(o.w, 0.f);
        out4[(long)row * 32 + lane] = o;
    }
}

// ---------------------------------------------------------------------------
extern "C" void kernel_launch(void* const* d_in, const int* in_sizes, int n_in,
                              void* d_out, int out_size) {
    const float* X  = (const float*)d_in[0];
    const void*  EI = d_in[1];
    const float* EF = (const float*)d_in[2];
    const float* W  = (const float*)d_in[3];
    const float* b  = (const float*)d_in[4];
    const float* We = (const float*)d_in[5];
    const float* be = (const float*)d_in[6];
    float* out = (float*)d_out;

    int N = in_sizes[0] / F;
    int E = in_sizes[2] / EFD;

    cudaFuncSetAttribute(k5_final, cudaFuncAttributeMaxDynamicSharedMemorySize,
                         K5_SMEM);

    k_prep<<<PREP_BLOCKS, PREP_T>>>(EI, N, E);
    k4_aggregate<<<(N * 32 + 255) / 256, 256>>>((const float4*)X, EF, N);
    int nGroups = (N + FRPW - 1) / FRPW;                 // 6250
    int k5b = (nGroups + K5W - 1) / K5W;                 // 782
    k5_final<<<k5b, K5T, K5_SMEM>>>((const float4*)W, (const float4*)b,
                                    (const float4*)We, (const float4*)be,
                                    (float4*)out, N);
}

// round 9
// speedup vs baseline: 1.0828x; 1.0828x over previous
#include <cuda_runtime.h>
#include <cuda_bf16.h>

#define NMAX 50000
#define EMAX 800000
#define F 128
#define EFD 6
#define SCAN_T 256

// ---- packed dual-fp32 ops (Blackwell f32x2) --------------------------------
#define PACK_F32X2(d, a, b) \
    asm("mov.b64 %0, {%1, %2};" : "=l"(d) : "f"(a), "f"(b))
#define FMA_F32X2(d, a, b, c) \
    asm("fma.rn.f32x2 %0, %1, %2, %3;" : "=l"(d) : "l"(a), "l"(b), "l"(c))
#define UNPACK_F32X2(lo, hi, v) \
    asm("mov.b64 {%0, %1}, %2;" : "=f"(lo), "=f"(hi) : "l"(v))

// ---------------- device scratch ----------------
__device__ int    g_is64;
__device__ int    g_counts[NMAX];
__device__ int    g_cursor[NMAX];
__device__ int    g_rowptr[NMAX + 1];
__device__ int    g_src[EMAX];
__device__ int    g_dst[EMAX];
__device__ int2   g_edges[EMAX];
__device__ float4 g_aggX[NMAX * (F / 4)];
__device__ float  g_aggE[NMAX * EFD];
__device__ int    g_blocksum[256];
__device__ int    g_blockoff[256];

// ---------------- K0: zero counts + detect index width ---------------------
__global__ void k0_zero_detect(const void* __restrict__ ei, int N, int E) {
    int i = blockIdx.x * blockDim.x + threadIdx.x;
    if (i < N) g_counts[i] = 0;
    if (i == 0) {
        const long long* p = (const long long*)ei;
        int ok = 1;
        int lim = E < 128 ? E : 128;
        for (int j = 0; j < lim; j++) {
            long long v = p[j];
            if (v < 0 || v >= (long long)N) { ok = 0; break; }
        }
        g_is64 = ok;
    }
}

// ---------------- K1: decode edgeIndex + histogram of dst ------------------
__global__ void k1_decode_hist(const void* __restrict__ ei, int E) {
    int e = blockIdx.x * blockDim.x + threadIdx.x;
    if (e >= E) return;
    int s, d;
    if (g_is64) {
        const longlong2* p = (const longlong2*)ei;
        longlong2 v = p[e];
        s = (int)v.x; d = (int)v.y;
    } else {
        const int2* p = (const int2*)ei;
        int2 v = p[e];
        s = v.x; d = v.y;
    }
    g_src[e] = s;
    g_dst[e] = d;
    atomicAdd(&g_counts[d], 1);
}

// ---------------- K2a/b/c: multi-block exclusive scan ------------------------
__device__ __forceinline__ int block_scan_256(int v, int* ws) {
    int t = threadIdx.x, lane = t & 31, wid = t >> 5;
    int x = v;
    #pragma unroll
    for (int o = 1; o < 32; o <<= 1) {
        int y = __shfl_up_sync(0xffffffffu, x, o);
        if (lane >= o) x += y;
    }
    if (lane == 31) ws[wid] = x;
    __syncthreads();
    if (wid == 0 && lane < 8) {
        int y = ws[lane];
        #pragma unroll
        for (int o = 1; o < 8; o <<= 1) {
            int z = __shfl_up_sync(0x000000ffu, y, o);
            if (lane >= o) y += z;
        }
        ws[lane] = y;
    }
    __syncthreads();
    return x + (wid > 0 ? ws[wid - 1] : 0);
}

__global__ void k2a_tile_scan(int N) {
    __shared__ int ws[8];
    int i = blockIdx.x * SCAN_T + threadIdx.x;
    int v = (i < N) ? g_counts[i] : 0;
    int incl = block_scan_256(v, ws);
    if (i < N) g_rowptr[i] = incl - v;
    if (threadIdx.x == 0) g_blocksum[blockIdx.x] = ws[7];
}

__global__ void k2b_blocksum_scan(int B, int N) {
    __shared__ int ws[8];
    int t = threadIdx.x;
    int v = (t < B) ? g_blocksum[t] : 0;
    int incl = block_scan_256(v, ws);
    if (t < B) g_blockoff[t] = incl - v;
    if (t == 0) g_rowptr[N] = ws[7];
}

__global__ void k2c_add_offsets(int N) {
    int i = blockIdx.x * blockDim.x + threadIdx.x;
    if (i < N) {
        int r = g_rowptr[i] + g_blockoff[i >> 8];
        g_rowptr[i] = r;
        g_cursor[i] = r;
    }
}

// ---------------- K3: scatter edges into CSR slots (MLP=4) ------------------
__global__ void k3_scatter(int E) {
    int e0 = (blockIdx.x * blockDim.x + threadIdx.x) * 4;
    int d[4], s[4];
    #pragma unroll
    for (int j = 0; j < 4; j++) {
        int e = e0 + j;
        if (e < E) { d[j] = g_dst[e]; s[j] = g_src[e]; }
    }
    #pragma unroll
    for (int j = 0; j < 4; j++) {
        int e = e0 + j;
        if (e < E) {
            int p = atomicAdd(&g_cursor[d[j]], 1);
            g_edges[p] = make_int2(s[j], e);
        }
    }
}

// ---------------- K4: warp-per-node aggregation (plain loads, L1 on) --------
__global__ void __launch_bounds__(256)
k4_aggregate(const float4* __restrict__ X4, const float* __restrict__ eF,
             int N) {
    int gwarp = (blockIdx.x * blockDim.x + threadIdx.x) >> 5;
    int lane  = threadIdx.x & 31;
    if (gwarp >= N) return;
    int v = gwarp;
    int s0 = g_rowptr[v], s1 = g_rowptr[v + 1];
    float4 acc = make_float4(0.f, 0.f, 0.f, 0.f);
    float ae = 0.f;
    for (int base = s0; base < s1; base += 32) {
        int cnt = s1 - base; if (cnt > 32) cnt = 32;
        int2 se = g_edges[base + (lane < cnt ? lane : 0)];
        for (int j = 0; j < cnt; j += 8) {
            #pragma unroll
            for (int u = 0; u < 8; u++) {
                if (j + u < cnt) {  // uniform across warp
                    int sj = __shfl_sync(0xffffffffu, se.x, j + u);
                    int ej = __shfl_sync(0xffffffffu, se.y, j + u);
                    float4 xv = X4[(long)sj * 32 + lane];
                    acc.x += xv.x; acc.y += xv.y;
                    acc.z += xv.z; acc.w += xv.w;
                    if (lane < EFD) ae += eF[(long)ej * EFD + lane];
                }
            }
        }
    }
    g_aggX[(long)v * 32 + lane] = acc;
    if (lane < EFD) g_aggE[v * EFD + lane] = ae;
}

// ---------------- K5: f32x2 GEMM + edge GEMM + bias*deg + relu --------------
#define K5T 256
#define K5W 8                 // warps/block
#define FRPW 8                // rows/warp
#define K5_SMEM (K5W * FRPW * 64 * 16)   // dup-pair staging: 64 KB

__global__ void __launch_bounds__(K5T)
k5_final(const float4* __restrict__ W4, const float4* __restrict__ b4p,
         const float4* __restrict__ We4, const float4* __restrict__ be4,
         float4* __restrict__ out4, int N) {
    extern __shared__ float4 xsd[];
    int tid = threadIdx.x, warp = tid >> 5, lane = tid & 31;
    float4* xw = xsd + warp * (FRPW * 64);

    int row0 = (blockIdx.x * K5W + warp) * FRPW;
    if (row0 >= N) return;

    #pragma unroll
    for (int r = 0; r < FRPW; r++) {
        int row = row0 + r;
        float4 a = (row < N) ? __ldcg(&g_aggX[(long)row * 32 + lane])
                             : make_float4(0.f, 0.f, 0.f, 0.f);
        xw[r * 64 + 2 * lane]     = make_float4(a.x, a.x, a.y, a.y);
        xw[r * 64 + 2 * lane + 1] = make_float4(a.z, a.z, a.w, a.w);
    }
    __syncwarp();

    unsigned long long a01[FRPW], a23[FRPW];
    #pragma unroll
    for (int r = 0; r < FRPW; r++) { a01[r] = 0ULL; a23[r] = 0ULL; }

    for (int kb = 0; kb < F; kb += 4) {
        unsigned long long w01[4], w23[4];
        #pragma unroll
        for (int kk = 0; kk < 4; kk++) {
            float4 w4 = __ldg(&W4[(kb + kk) * 32 + lane]);
            PACK_F32X2(w01[kk], w4.x, w4.y);
            PACK_F32X2(w23[kk], w4.z, w4.w);
        }
        #pragma unroll
        for (int r = 0; r < FRPW; r++) {
            ulonglong2 xa = *(const ulonglong2*)&xw[r * 64 + (kb >> 1)];
            ulonglong2 xb = *(const ulonglong2*)&xw[r * 64 + (kb >> 1) + 1];
            FMA_F32X2(a01[r], xa.x, w01[0], a01[r]);
            FMA_F32X2(a23[r], xa.x, w23[0], a23[r]);
            FMA_F32X2(a01[r], xa.y, w01[1], a01[r]);
            FMA_F32X2(a23[r], xa.y, w23[1], a23[r]);
            FMA_F32X2(a01[r], xb.x, w01[2], a01[r]);
            FMA_F32X2(a23[r], xb.x, w23[2], a23[r]);
            FMA_F32X2(a01[r], xb.y, w01[3], a01[r]);
            FMA_F32X2(a23[r], xb.y, w23[3], a23[r]);
        }
    }

    float4 bb = __ldg(&b4p[lane]);
    float4 be = __ldg(&be4[lane]);
    float4 bs = make_float4(bb.x + be.x, bb.y + be.y, bb.z + be.z, bb.w + be.w);
    #pragma unroll
    for (int r = 0; r < FRPW; r++) {
        int row = row0 + r;
        if (row >= N) break;
        float deg = (float)(g_rowptr[row + 1] - g_rowptr[row]);
        float4 o;
        UNPACK_F32X2(o.x, o.y, a01[r]);
        UNPACK_F32X2(o.z, o.w, a23[r]);
        o.x = fmaf(deg, bs.x, o.x);
        o.y = fmaf(deg, bs.y, o.y);
        o.z = fmaf(deg, bs.z, o.z);
        o.w = fmaf(deg, bs.w, o.w);
        #pragma unroll
        for (int k = 0; k < EFD; k++) {
            float ek = g_aggE[row * EFD + k];
            float4 w4 = __ldg(&We4[k * 32 + lane]);
            o.x = fmaf(ek, w4.x, o.x);
            o.y = fmaf(ek, w4.y, o.y);
            o.z = fmaf(ek, w4.z, o.z);
            o.w = fmaf(ek, w4.w, o.w);
        }
        o.x = fmaxf(o.x, 0.f); o.y = fmaxf(o.y, 0.f);
        o.z = fmaxf(o.z, 0.f); o.w = fmaxf(o.w, 0.f);
        out4[(long)row * 32 + lane] = o;
    }
}

// ---------------------------------------------------------------------------
extern "C" void kernel_launch(void* const* d_in, const int* in_sizes, int n_in,
                              void* d_out, int out_size) {
    const float* X  = (const float*)d_in[0];
    const void*  EI = d_in[1];
    const float* EF = (const float*)d_in[2];
    const float* W  = (const float*)d_in[3];
    const float* b  = (const float*)d_in[4];
    const float* We = (const float*)d_in[5];
    const float* be = (const float*)d_in[6];
    float* out = (float*)d_out;

    int N = in_sizes[0] / F;
    int E = in_sizes[2] / EFD;
    int B = (N + SCAN_T - 1) / SCAN_T;

    cudaFuncSetAttribute(k5_final, cudaFuncAttributeMaxDynamicSharedMemorySize,
                         K5_SMEM);

    k0_zero_detect<<<(N + 255) / 256, 256>>>(EI, N, E);
    k1_decode_hist<<<(E + 255) / 256, 256>>>(EI, E);
    k2a_tile_scan<<<B, SCAN_T>>>(N);
    k2b_blocksum_scan<<<1, SCAN_T>>>(B, N);
    k2c_add_offsets<<<B, SCAN_T>>>(N);
    k3_scatter<<<(E + 1023) / 1024, 256>>>(E);
    k4_aggregate<<<(N * 32 + 255) / 256, 256>>>((const float4*)X, EF, N);
    int nGroups = (N + FRPW - 1) / FRPW;
    int k5b = (nGroups + K5W - 1) / K5W;
    k5_final<<<k5b, K5T, K5_SMEM>>>((const float4*)W, (const float4*)b,
                                    (const float4*)We, (const float4*)be,
                                    (float4*)out, N);
}

// round 10
// speedup vs baseline: 1.2425x; 1.1474x over previous
#include <cuda_runtime.h>
#include <cuda_bf16.h>

#define NMAX 50000
#define EMAX 800000
#define F 128
#define EFD 6
#define SCAN_T 256

// ---- packed dual-fp32 ops (Blackwell f32x2) --------------------------------
#define PACK_F32X2(d, a, b) \
    asm("mov.b64 %0, {%1, %2};" : "=l"(d) : "f"(a), "f"(b))
#define FMA_F32X2(d, a, b, c) \
    asm("fma.rn.f32x2 %0, %1, %2, %3;" : "=l"(d) : "l"(a), "l"(b), "l"(c))
#define UNPACK_F32X2(lo, hi, v) \
    asm("mov.b64 {%0, %1}, %2;" : "=f"(lo), "=f"(hi) : "l"(v))

// ---------------- device scratch ----------------
__device__ int    g_is64;
__device__ int    g_counts[NMAX];
__device__ int    g_cursor[NMAX];
__device__ int    g_rowptr[NMAX + 1];
__device__ int    g_src[EMAX];
__device__ int    g_dst[EMAX];
__device__ int2   g_edges[EMAX];
__device__ float4 g_aggX[NMAX * (F / 4)];
__device__ float  g_aggE[NMAX * EFD];
__device__ int    g_blocksum[256];
__device__ int    g_blockoff[256];

// ---------------- K0: zero counts + PARALLEL index-width detect -------------
__global__ void k0_zero_detect(const void* __restrict__ ei, int N, int E) {
    int i = blockIdx.x * blockDim.x + threadIdx.x;
    if (i < N) g_counts[i] = 0;
    // warp 0 of block 0: check first 128 int64 words with 4 indep loads/lane
    if (blockIdx.x == 0 && threadIdx.x < 32) {
        const long long* p = (const long long*)ei;
        int lane = threadIdx.x;
        long long nwords = (long long)E * 2;       // entries if int64
        int bad = 0;
        #pragma unroll
        for (int j = 0; j < 4; j++) {
            long long idx = lane + j * 32;
            if (idx < nwords) {
                long long v = p[idx];
                if (v < 0 || v >= (long long)N) bad = 1;
            }
        }
        unsigned m = __ballot_sync(0xffffffffu, bad);
        if (lane == 0) g_is64 = (m == 0u) ? 1 : 0;
    }
}

// ---------------- K1: decode edgeIndex + histogram of dst ------------------
__global__ void k1_decode_hist(const void* __restrict__ ei, int E) {
    int e = blockIdx.x * blockDim.x + threadIdx.x;
    if (e >= E) return;
    int s, d;
    if (g_is64) {
        const longlong2* p = (const longlong2*)ei;
        longlong2 v = p[e];
        s = (int)v.x; d = (int)v.y;
    } else {
        const int2* p = (const int2*)ei;
        int2 v = p[e];
        s = v.x; d = v.y;
    }
    g_src[e] = s;
    g_dst[e] = d;
    atomicAdd(&g_counts[d], 1);
}

// ---------------- K2a/b/c: multi-block exclusive scan ------------------------
__device__ __forceinline__ int block_scan_256(int v, int* ws) {
    int t = threadIdx.x, lane = t & 31, wid = t >> 5;
    int x = v;
    #pragma unroll
    for (int o = 1; o < 32; o <<= 1) {
        int y = __shfl_up_sync(0xffffffffu, x, o);
        if (lane >= o) x += y;
    }
    if (lane == 31) ws[wid] = x;
    __syncthreads();
    if (wid == 0 && lane < 8) {
        int y = ws[lane];
        #pragma unroll
        for (int o = 1; o < 8; o <<= 1) {
            int z = __shfl_up_sync(0x000000ffu, y, o);
            if (lane >= o) y += z;
        }
        ws[lane] = y;
    }
    __syncthreads();
    return x + (wid > 0 ? ws[wid - 1] : 0);
}

__global__ void k2a_tile_scan(int N) {
    __shared__ int ws[8];
    int i = blockIdx.x * SCAN_T + threadIdx.x;
    int v = (i < N) ? g_counts[i] : 0;
    int incl = block_scan_256(v, ws);
    if (i < N) g_rowptr[i] = incl - v;
    if (threadIdx.x == 0) g_blocksum[blockIdx.x] = ws[7];
}

__global__ void k2b_blocksum_scan(int B, int N) {
    __shared__ int ws[8];
    int t = threadIdx.x;
    int v = (t < B) ? g_blocksum[t] : 0;
    int incl = block_scan_256(v, ws);
    if (t < B) g_blockoff[t] = incl - v;
    if (t == 0) g_rowptr[N] = ws[7];
}

__global__ void k2c_add_offsets(int N) {
    int i = blockIdx.x * blockDim.x + threadIdx.x;
    if (i < N) {
        int r = g_rowptr[i] + g_blockoff[i >> 8];
        g_rowptr[i] = r;
        g_cursor[i] = r;
    }
}

// ---------------- K3: scatter edges into CSR slots (MLP=4) ------------------
__global__ void k3_scatter(int E) {
    int e0 = (blockIdx.x * blockDim.x + threadIdx.x) * 4;
    int d[4], s[4];
    #pragma unroll
    for (int j = 0; j < 4; j++) {
        int e = e0 + j;
        if (e < E) { d[j] = g_dst[e]; s[j] = g_src[e]; }
    }
    #pragma unroll
    for (int j = 0; j < 4; j++) {
        int e = e0 + j;
        if (e < E) {
            int p = atomicAdd(&g_cursor[d[j]], 1);
            g_edges[p] = make_int2(s[j], e);
        }
    }
}

// ---------------- K4: warp-per-node aggregation (round-2 exact) -------------
__global__ void k4_aggregate(const float4* __restrict__ X4,
                             const float* __restrict__ eF, int N) {
    int gwarp = (blockIdx.x * blockDim.x + threadIdx.x) >> 5;
    int lane  = threadIdx.x & 31;
    int nwarp = (gridDim.x * blockDim.x) >> 5;
    for (int v = gwarp; v < N; v += nwarp) {
        int s0 = g_rowptr[v], s1 = g_rowptr[v + 1];
        float4 acc = make_float4(0.f, 0.f, 0.f, 0.f);
        float ae = 0.f;
        for (int base = s0; base < s1; base += 32) {
            int cnt = s1 - base; if (cnt > 32) cnt = 32;
            int2 se = g_edges[base + (lane < cnt ? lane : 0)];
            for (int j = 0; j < cnt; j += 4) {
                #pragma unroll
                for (int u = 0; u < 4; u++) {
                    if (j + u < cnt) {  // uniform across warp
                        int sj = __shfl_sync(0xffffffffu, se.x, j + u);
                        int ej = __shfl_sync(0xffffffffu, se.y, j + u);
                        float4 xv = X4[(long)sj * 32 + lane];
                        acc.x += xv.x; acc.y += xv.y;
                        acc.z += xv.z; acc.w += xv.w;
                        if (lane < EFD) ae += eF[(long)ej * EFD + lane];
                    }
                }
            }
        }
        g_aggX[(long)v * 32 + lane] = acc;
        if (lane < EFD) g_aggE[v * EFD + lane] = ae;
    }
}

// ---------------- K5: persistent f32x2 GEMM, packed-W smem ------------------
#define K5T 512
#define K5W (K5T / 32)         // 16 warps
#define FRPW 8                 // rows per warp
// smem: Wp[128][32] ulonglong2 (64KB) + staging 16w x 8r x 64 float4 (128KB)
#define K5_SMEM (F * 32 * 16 + K5W * FRPW * 64 * 16)

__global__ void __launch_bounds__(K5T)
k5_final(const float4* __restrict__ W4, const float4* __restrict__ b4p,
         const float4* __restrict__ We4, const float4* __restrict__ be4,
         float4* __restrict__ out4, int N) {
    extern __shared__ char smem[];
    ulonglong2* Wp = (ulonglong2*)smem;                    // [k][lane]
    float4*     xs = (float4*)(smem + F * 32 * 16);        // [warp][row*64]

    int tid = threadIdx.x, warp = tid >> 5, lane = tid & 31;

    // pack W into smem as (w01, w23) pairs
    for (int idx = tid; idx < F * 32; idx += K5T) {
        float4 w4 = __ldg(&W4[idx]);
        ulonglong2 p;
        PACK_F32X2(p.x, w4.x, w4.y);
        PACK_F32X2(p.y, w4.z, w4.w);
        Wp[idx] = p;
    }
    __syncthreads();

    float4* xw = xs + warp * (FRPW * 64);
    float4 bb = __ldg(&b4p[lane]);
    float4 bev = __ldg(&be4[lane]);
    float4 bs = make_float4(bb.x + bev.x, bb.y + bev.y,
                            bb.z + bev.z, bb.w + bev.w);

    int nGroups = (N + FRPW - 1) / FRPW;
    for (int g = blockIdx.x * K5W + warp; g < nGroups; g += gridDim.x * K5W) {
        int row0 = g * FRPW;
        int nr = N - row0; if (nr > FRPW) nr = FRPW;

        // stage rows as dup pairs
        #pragma unroll
        for (int r = 0; r < FRPW; r++) {
            int row = row0 + (r < nr ? r : 0);
            float4 a = g_aggX[(long)row * 32 + lane];
            xw[r * 64 + 2 * lane]     = make_float4(a.x, a.x, a.y, a.y);
            xw[r * 64 + 2 * lane + 1] = make_float4(a.z, a.z, a.w, a.w);
        }
        __syncwarp();

        unsigned long long a01[FRPW], a23[FRPW];
        #pragma unroll
        for (int r = 0; r < FRPW; r++) { a01[r] = 0ULL; a23[r] = 0ULL; }

        for (int kb = 0; kb < F; kb += 4) {
            ulonglong2 w[4];
            #pragma unroll
            for (int kk = 0; kk < 4; kk++)
                w[kk] = Wp[(kb + kk) * 32 + lane];        // LDS.128
            #pragma unroll
            for (int r = 0; r < FRPW; r++) {
                ulonglong2 xa = *(const ulonglong2*)&xw[r * 64 + (kb >> 1)];
                ulonglong2 xb = *(const ulonglong2*)&xw[r * 64 + (kb >> 1) + 1];
                FMA_F32X2(a01[r], xa.x, w[0].x, a01[r]);
                FMA_F32X2(a23[r], xa.x, w[0].y, a23[r]);
                FMA_F32X2(a01[r], xa.y, w[1].x, a01[r]);
                FMA_F32X2(a23[r], xa.y, w[1].y, a23[r]);
                FMA_F32X2(a01[r], xb.x, w[2].x, a01[r]);
                FMA_F32X2(a23[r], xb.x, w[2].y, a23[r]);
                FMA_F32X2(a01[r], xb.y, w[3].x, a01[r]);
                FMA_F32X2(a23[r], xb.y, w[3].y, a23[r]);
            }
        }

        for (int r = 0; r < nr; r++) {
            int row = row0 + r;
            float deg = (float)(g_rowptr[row + 1] - g_rowptr[row]);
            float4 o;
            UNPACK_F32X2(o.x, o.y, a01[r]);
            UNPACK_F32X2(o.z, o.w, a23[r]);
            o.x = fmaf(deg, bs.x, o.x);
            o.y = fmaf(deg, bs.y, o.y);
            o.z = fmaf(deg, bs.z, o.z);
            o.w = fmaf(deg, bs.w, o.w);
            #pragma unroll
            for (int k = 0; k < EFD; k++) {
                float ek = g_aggE[row * EFD + k];
                float4 w4 = __ldg(&We4[k * 32 + lane]);
                o.x = fmaf(ek, w4.x, o.x);
                o.y = fmaf(ek, w4.y, o.y);
                o.z = fmaf(ek, w4.z, o.z);
                o.w = fmaf(ek, w4.w, o.w);
            }
            o.x = fmaxf(o.x, 0.f); o.y = fmaxf(o.y, 0.f);
            o.z = fmaxf(o.z, 0.f); o.w = fmaxf(o.w, 0.f);
            out4[(long)row * 32 + lane] = o;
        }
        __syncwarp();
    }
}

// ---------------------------------------------------------------------------
extern "C" void kernel_launch(void* const* d_in, const int* in_sizes, int n_in,
                              void* d_out, int out_size) {
    const float* X  = (const float*)d_in[0];
    const void*  EI = d_in[1];
    const float* EF = (const float*)d_in[2];
    const float* W  = (const float*)d_in[3];
    const float* b  = (const float*)d_in[4];
    const float* We = (const float*)d_in[5];
    const float* be = (const float*)d_in[6];
    float* out = (float*)d_out;

    int N = in_sizes[0] / F;
    int E = in_sizes[2] / EFD;
    int B = (N + SCAN_T - 1) / SCAN_T;

    cudaFuncSetAttribute(k5_final, cudaFuncAttributeMaxDynamicSharedMemorySize,
                         K5_SMEM);

    k0_zero_detect<<<(N + 255) / 256, 256>>>(EI, N, E);
    k1_decode_hist<<<(E + 255) / 256, 256>>>(EI, E);
    k2a_tile_scan<<<B, SCAN_T>>>(N);
    k2b_blocksum_scan<<<1, SCAN_T>>>(B, N);
    k2c_add_offsets<<<B, SCAN_T>>>(N);
    k3_scatter<<<(E + 1023) / 1024, 256>>>(E);
    k4_aggregate<<<(N * 32 + 255) / 256, 256>>>((const float4*)X, EF, N);
    k5_final<<<148, K5T, K5_SMEM>>>((const float4*)W, (const float4*)b,
                                    (const float4*)We, (const float4*)be,
                                    (float4*)out, N);
}

// round 11
// speedup vs baseline: 1.3266x; 1.0677x over previous
#include <cuda_runtime.h>
#include <cuda_bf16.h>

#define NMAX 50000
#define EMAX 800000
#define F 128
#define EFD 6
#define SCAN_T 256

// ---------------- device scratch ----------------
__device__ int    g_counts[NMAX];
__device__ int    g_cursor[NMAX];
__device__ int    g_rowptr[NMAX];     // region start (NOT globally monotonic)
__device__ int    g_rowend[NMAX];     // region end
__device__ int    g_src[EMAX];
__device__ int    g_dst[EMAX];
__device__ int2   g_edges[EMAX];
__device__ float4 g_aggX[NMAX * (F / 4)];
__device__ float  g_aggE[NMAX * EFD];
__device__ int    g_total;            // tile-base allocator (reset in k1)

// ---------------- K1: decode + histogram (per-block width detect) -----------
__global__ void __launch_bounds__(256)
k1_decode_hist(const void* __restrict__ ei, int N, int E) {
    __shared__ int s_is64;
    int t = threadIdx.x;
    // warp 0: probe first 128 words as int64; all in [0,N) => int64 layout
    if (t < 32) {
        const long long* p = (const long long*)ei;
        long long nwords = (long long)E * 2;
        int bad = 0;
        #pragma unroll
        for (int j = 0; j < 4; j++) {
            long long idx = t + j * 32;
            if (idx < nwords) {
                long long v = p[idx];
                if (v < 0 || v >= (long long)N) bad = 1;
            }
        }
        unsigned m = __ballot_sync(0xffffffffu, bad);
        if (t == 0) s_is64 = (m == 0u) ? 1 : 0;
    }
    __syncthreads();

    int e = blockIdx.x * blockDim.x + t;
    if (blockIdx.x == 0 && t == 0) g_total = 0;   // reset allocator for k2
    if (e >= E) return;
    int s, d;
    if (s_is64) {
        const longlong2* p = (const longlong2*)ei;
        longlong2 v = p[e];
        s = (int)v.x; d = (int)v.y;
    } else {
        const int2* p = (const int2*)ei;
        int2 v = p[e];
        s = v.x; d = v.y;
    }
    g_src[e] = s;
    g_dst[e] = d;
    atomicAdd(&g_counts[d], 1);
}

// ---------------- K2: single-kernel scan (atomic tile base) + re-zero -------
__global__ void __launch_bounds__(SCAN_T)
k2_scan(int N) {
    __shared__ int ws[8];
    __shared__ int s_base;
    int t = threadIdx.x, lane = t & 31, wid = t >> 5;
    int i = blockIdx.x * SCAN_T + t;
    int v = (i < N) ? g_counts[i] : 0;

    // inclusive scan of v across 256 threads; ws[7] = tile total
    int x = v;
    #pragma unroll
    for (int o = 1; o < 32; o <<= 1) {
        int y = __shfl_up_sync(0xffffffffu, x, o);
        if (lane >= o) x += y;
    }
    if (lane == 31) ws[wid] = x;
    __syncthreads();
    if (wid == 0 && lane < 8) {
        int y = ws[lane];
        #pragma unroll
        for (int o = 1; o < 8; o <<= 1) {
            int z = __shfl_up_sync(0x000000ffu, y, o);
            if (lane >= o) y += z;
        }
        ws[lane] = y;
    }
    __syncthreads();
    int incl = x + (wid > 0 ? ws[wid - 1] : 0);

    if (t == 0) s_base = atomicAdd(&g_total, ws[7]);   // grab region base
    __syncthreads();

    if (i < N) {
        int start = s_base + incl - v;
        g_rowptr[i] = start;
        g_rowend[i] = start + v;
        g_cursor[i] = start;
        g_counts[i] = 0;            // ready for next graph replay
    }
}

// ---------------- K3: scatter edges into CSR slots (MLP=8) ------------------
__global__ void __launch_bounds__(256)
k3_scatter(int E) {
    int e0 = (blockIdx.x * blockDim.x + threadIdx.x) * 8;
    int d[8], s[8];
    #pragma unroll
    for (int j = 0; j < 8; j++) {
        int e = e0 + j;
        if (e < E) { d[j] = g_dst[e]; s[j] = g_src[e]; }
    }
    #pragma unroll
    for (int j = 0; j < 8; j++) {
        int e = e0 + j;
        if (e < E) {
            int p = atomicAdd(&g_cursor[d[j]], 1);
            g_edges[p] = make_int2(s[j], e);
        }
    }
}

// ---------------- K4: warp-per-node aggregation (round-2 exact) -------------
__global__ void k4_aggregate(const float4* __restrict__ X4,
                             const float* __restrict__ eF, int N) {
    int gwarp = (blockIdx.x * blockDim.x + threadIdx.x) >> 5;
    int lane  = threadIdx.x & 31;
    int nwarp = (gridDim.x * blockDim.x) >> 5;
    for (int v = gwarp; v < N; v += nwarp) {
        int s0 = g_rowptr[v], s1 = g_rowend[v];
        float4 acc = make_float4(0.f, 0.f, 0.f, 0.f);
        float ae = 0.f;
        for (int base = s0; base < s1; base += 32) {
            int cnt = s1 - base; if (cnt > 32) cnt = 32;
            int2 se = g_edges[base + (lane < cnt ? lane : 0)];
            for (int j = 0; j < cnt; j += 4) {
                #pragma unroll
                for (int u = 0; u < 4; u++) {
                    if (j + u < cnt) {  // uniform across warp
                        int sj = __shfl_sync(0xffffffffu, se.x, j + u);
                        int ej = __shfl_sync(0xffffffffu, se.y, j + u);
                        float4 xv = X4[(long)sj * 32 + lane];
                        acc.x += xv.x; acc.y += xv.y;
                        acc.z += xv.z; acc.w += xv.w;
                        if (lane < EFD) ae += eF[(long)ej * EFD + lane];
                    }
                }
            }
        }
        g_aggX[(long)v * 32 + lane] = acc;
        if (lane < EFD) g_aggE[v * EFD + lane] = ae;
    }
}

// ---------------- K5: round-2 exact persistent GEMM + relu ------------------
#define K5_THREADS 512
#define K5_RPW 8
#define K5_SMEM ((F*F + EFD*F + F) * 4 + (K5_THREADS/32) * K5_RPW * F * 4)

__global__ void __launch_bounds__(K5_THREADS)
k5_final(const float* __restrict__ W, const float* __restrict__ b,
         const float* __restrict__ We, const float* __restrict__ be,
         float* __restrict__ out, int N) {
    extern __shared__ float smem[];
    float*  Ws   = smem;
    float*  Wes  = Ws + F * F;
    float*  bsum = Wes + EFD * F;
    float4* xs   = (float4*)(bsum + F);

    int tid = threadIdx.x;
    for (int i = tid; i < F * F; i += K5_THREADS) Ws[i] = W[i];
    for (int i = tid; i < EFD * F; i += K5_THREADS) Wes[i] = We[i];
    for (int i = tid; i < F; i += K5_THREADS) bsum[i] = b[i] + be[i];
    __syncthreads();

    int warp = tid >> 5, lane = tid & 31;
    float4* xw4 = xs + warp * (K5_RPW * 32);
    const float* xw = (const float*)xw4;

    int nGroups = (N + K5_RPW - 1) / K5_RPW;
    for (int g = blockIdx.x * (K5_THREADS / 32) + warp; g < nGroups;
         g += gridDim.x * (K5_THREADS / 32)) {
        int row0 = g * K5_RPW;
        int nr = N - row0; if (nr > K5_RPW) nr = K5_RPW;
        #pragma unroll
        for (int r = 0; r < K5_RPW; r++) {
            int row = row0 + (r < nr ? r : 0);
            xw4[r * 32 + lane] = g_aggX[(long)row * 32 + lane];
        }
        __syncwarp();

        float4 acc[K5_RPW];
        #pragma unroll
        for (int r = 0; r < K5_RPW; r++) acc[r] = make_float4(0.f, 0.f, 0.f, 0.f);

        #pragma unroll 2
        for (int k = 0; k < F; k += 4) {
            float4 xv[K5_RPW];
            #pragma unroll
            for (int r = 0; r < K5_RPW; r++)
                xv[r] = *(const float4*)(xw + (r << 7) + k);
            #pragma unroll
            for (int kk = 0; kk < 4; kk++) {
                float4 w4 = ((const float4*)(Ws + ((k + kk) << 7)))[lane];
                #pragma unroll
                for (int r = 0; r < K5_RPW; r++) {
                    float xk = (kk == 0) ? xv[r].x : (kk == 1) ? xv[r].y
                             : (kk == 2) ? xv[r].z : xv[r].w;
                    acc[r].x = fmaf(xk, w4.x, acc[r].x);
                    acc[r].y = fmaf(xk, w4.y, acc[r].y);
                    acc[r].z = fmaf(xk, w4.z, acc[r].z);
                    acc[r].w = fmaf(xk, w4.w, acc[r].w);
                }
            }
        }

        float4 b4 = ((const float4*)bsum)[lane];
        for (int r = 0; r < nr; r++) {
            int row = row0 + r;
            float deg = (float)(g_rowend[row] - g_rowptr[row]);
            float4 o = acc[r];
            o.x = fmaf(deg, b4.x, o.x);
            o.y = fmaf(deg, b4.y, o.y);
            o.z = fmaf(deg, b4.z, o.z);
            o.w = fmaf(deg, b4.w, o.w);
            #pragma unroll
            for (int k = 0; k < EFD; k++) {
                float ek = g_aggE[row * EFD + k];
                float4 w4 = ((const float4*)(Wes + (k << 7)))[lane];
                o.x = fmaf(ek, w4.x, o.x);
                o.y = fmaf(ek, w4.y, o.y);
                o.z = fmaf(ek, w4.z, o.z);
                o.w = fmaf(ek, w4.w, o.w);
            }
            o.x = fmaxf(o.x, 0.f); o.y = fmaxf(o.y, 0.f);
            o.z = fmaxf(o.z, 0.f); o.w = fmaxf(o.w, 0.f);
            ((float4*)out)[(long)row * 32 + lane] = o;
        }
        __syncwarp();
    }
}

// ---------------------------------------------------------------------------
extern "C" void kernel_launch(void* const* d_in, const int* in_sizes, int n_in,
                              void* d_out, int out_size) {
    const float* X  = (const float*)d_in[0];
    const void*  EI = d_in[1];
    const float* EF = (const float*)d_in[2];
    const float* W  = (const float*)d_in[3];
    const float* b  = (const float*)d_in[4];
    const float* We = (const float*)d_in[5];
    const float* be = (const float*)d_in[6];
    float* out = (float*)d_out;

    int N = in_sizes[0] / F;
    int E = in_sizes[2] / EFD;
    int B = (N + SCAN_T - 1) / SCAN_T;

    cudaFuncSetAttribute(k5_final, cudaFuncAttributeMaxDynamicSharedMemorySize,
                         K5_SMEM);

    k1_decode_hist<<<(E + 255) / 256, 256>>>(EI, N, E);
    k2_scan<<<B, SCAN_T>>>(N);
    k3_scatter<<<(E + 2047) / 2048, 256>>>(E);
    k4_aggregate<<<(N * 32 + 255) / 256, 256>>>((const float4*)X, EF, N);
    k5_final<<<148, K5_THREADS, K5_SMEM>>>(W, b, We, be, out, N);
}

// round 12
// speedup vs baseline: 1.3480x; 1.0161x over previous
#include <cuda_runtime.h>
#include <cuda_bf16.h>

#define NMAX 50000
#define EMAX 800000
#define F 128
#define EFD 6
#define SCAN_T 256

// ---- packed dual-fp32 ops (Blackwell f32x2) --------------------------------
#define PACK_F32X2(d, a, b) \
    asm("mov.b64 %0, {%1, %2};" : "=l"(d) : "f"(a), "f"(b))
#define FMA_F32X2(d, a, b, c) \
    asm("fma.rn.f32x2 %0, %1, %2, %3;" : "=l"(d) : "l"(a), "l"(b), "l"(c))
#define UNPACK_F32X2(lo, hi, v) \
    asm("mov.b64 {%0, %1}, %2;" : "=f"(lo), "=f"(hi) : "l"(v))

// ---------------- device scratch ----------------
__device__ int    g_counts[NMAX];
__device__ int    g_cursor[NMAX];
__device__ int    g_rowptr[NMAX];     // region start (NOT globally monotonic)
__device__ int    g_rowend[NMAX];     // region end
__device__ int    g_src[EMAX];
__device__ int    g_dst[EMAX];
__device__ int2   g_edges[EMAX];
__device__ float4 g_aggX[NMAX * (F / 4)];
__device__ float  g_aggE[NMAX * EFD];
__device__ int    g_total;            // tile-base allocator (reset in k1)

// ---------------- K1: decode + histogram (per-block width detect) -----------
__global__ void __launch_bounds__(256)
k1_decode_hist(const void* __restrict__ ei, int N, int E) {
    __shared__ int s_is64;
    int t = threadIdx.x;
    if (t < 32) {
        const long long* p = (const long long*)ei;
        long long nwords = (long long)E * 2;
        int bad = 0;
        #pragma unroll
        for (int j = 0; j < 4; j++) {
            long long idx = t + j * 32;
            if (idx < nwords) {
                long long v = p[idx];
                if (v < 0 || v >= (long long)N) bad = 1;
            }
        }
        unsigned m = __ballot_sync(0xffffffffu, bad);
        if (t == 0) s_is64 = (m == 0u) ? 1 : 0;
    }
    __syncthreads();

    int e = blockIdx.x * blockDim.x + t;
    if (blockIdx.x == 0 && t == 0) g_total = 0;
    if (e >= E) return;
    int s, d;
    if (s_is64) {
        const longlong2* p = (const longlong2*)ei;
        longlong2 v = p[e];
        s = (int)v.x; d = (int)v.y;
    } else {
        const int2* p = (const int2*)ei;
        int2 v = p[e];
        s = v.x; d = v.y;
    }
    g_src[e] = s;
    g_dst[e] = d;
    atomicAdd(&g_counts[d], 1);
}

// ---------------- K2: single-kernel scan (atomic tile base) + re-zero -------
__global__ void __launch_bounds__(SCAN_T)
k2_scan(int N) {
    __shared__ int ws[8];
    __shared__ int s_base;
    int t = threadIdx.x, lane = t & 31, wid = t >> 5;
    int i = blockIdx.x * SCAN_T + t;
    int v = (i < N) ? g_counts[i] : 0;

    int x = v;
    #pragma unroll
    for (int o = 1; o < 32; o <<= 1) {
        int y = __shfl_up_sync(0xffffffffu, x, o);
        if (lane >= o) x += y;
    }
    if (lane == 31) ws[wid] = x;
    __syncthreads();
    if (wid == 0 && lane < 8) {
        int y = ws[lane];
        #pragma unroll
        for (int o = 1; o < 8; o <<= 1) {
            int z = __shfl_up_sync(0x000000ffu, y, o);
            if (lane >= o) y += z;
        }
        ws[lane] = y;
    }
    __syncthreads();
    int incl = x + (wid > 0 ? ws[wid - 1] : 0);

    if (t == 0) s_base = atomicAdd(&g_total, ws[7]);
    __syncthreads();

    if (i < N) {
        int start = s_base + incl - v;
        g_rowptr[i] = start;
        g_rowend[i] = start + v;
        g_cursor[i] = start;
        g_counts[i] = 0;
    }
}

// ---------------- K3: scatter edges into CSR slots (MLP=8) ------------------
__global__ void __launch_bounds__(256)
k3_scatter(int E) {
    int e0 = (blockIdx.x * blockDim.x + threadIdx.x) * 8;
    int d[8], s[8];
    #pragma unroll
    for (int j = 0; j < 8; j++) {
        int e = e0 + j;
        if (e < E) { d[j] = g_dst[e]; s[j] = g_src[e]; }
    }
    #pragma unroll
    for (int j = 0; j < 8; j++) {
        int e = e0 + j;
        if (e < E) {
            int p = atomicAdd(&g_cursor[d[j]], 1);
            g_edges[p] = make_int2(s[j], e);
        }
    }
}

// ---------------- K4: warp-per-node aggregation ------------------------------
__global__ void k4_aggregate(const float4* __restrict__ X4,
                             const float* __restrict__ eF, int N) {
    int gwarp = (blockIdx.x * blockDim.x + threadIdx.x) >> 5;
    int lane  = threadIdx.x & 31;
    int nwarp = (gridDim.x * blockDim.x) >> 5;
    for (int v = gwarp; v < N; v += nwarp) {
        int s0 = g_rowptr[v], s1 = g_rowend[v];
        float4 acc = make_float4(0.f, 0.f, 0.f, 0.f);
        float ae = 0.f;
        for (int base = s0; base < s1; base += 32) {
            int cnt = s1 - base; if (cnt > 32) cnt = 32;
            int2 se = g_edges[base + (lane < cnt ? lane : 0)];
            for (int j = 0; j < cnt; j += 4) {
                #pragma unroll
                for (int u = 0; u < 4; u++) {
                    if (j + u < cnt) {  // uniform across warp
                        int sj = __shfl_sync(0xffffffffu, se.x, j + u);
                        int ej = __shfl_sync(0xffffffffu, se.y, j + u);
                        float4 xv = X4[(long)sj * 32 + lane];
                        acc.x += xv.x; acc.y += xv.y;
                        acc.z += xv.z; acc.w += xv.w;
                        if (lane < EFD) ae += eF[(long)ej * EFD + lane];
                    }
                }
            }
        }
        g_aggX[(long)v * 32 + lane] = acc;
        if (lane < EFD) g_aggE[v * EFD + lane] = ae;
    }
}

// ---------------- K5: persistent f32x2 GEMM (packed-W smem, plain-x stage) --
#define K5_THREADS 512
#define K5W (K5_THREADS / 32)   // 16 warps
#define K5_RPW 8
// smem: Wp 64KB | Wes 3KB | bsum 0.5KB | xs 64KB  ~= 131.5KB
#define K5_SMEM (F * 32 * 16 + EFD * F * 4 + F * 4 + K5W * K5_RPW * 32 * 16)

__global__ void __launch_bounds__(K5_THREADS)
k5_final(const float4* __restrict__ W4, const float* __restrict__ b,
         const float* __restrict__ We, const float* __restrict__ be,
         float* __restrict__ out, int N) {
    extern __shared__ char smem[];
    ulonglong2* Wp   = (ulonglong2*)smem;                       // [k][lane]
    float*      Wes  = (float*)(smem + F * 32 * 16);
    float*      bsum = Wes + EFD * F;
    float4*     xs   = (float4*)(bsum + F);

    int tid = threadIdx.x, warp = tid >> 5, lane = tid & 31;

    // pack W once: (w01, w23) f32x2 pairs, same 16B/4-col density as float4
    for (int idx = tid; idx < F * 32; idx += K5_THREADS) {
        float4 w4 = __ldg(&W4[idx]);
        ulonglong2 p;
        PACK_F32X2(p.x, w4.x, w4.y);
        PACK_F32X2(p.y, w4.z, w4.w);
        Wp[idx] = p;
    }
    for (int i = tid; i < EFD * F; i += K5_THREADS) Wes[i] = We[i];
    for (int i = tid; i < F; i += K5_THREADS) bsum[i] = b[i] + be[i];
    __syncthreads();

    float4* xw4 = xs + warp * (K5_RPW * 32);

    int nGroups = (N + K5_RPW - 1) / K5_RPW;
    for (int g = blockIdx.x * K5W + warp; g < nGroups; g += gridDim.x * K5W) {
        int row0 = g * K5_RPW;
        int nr = N - row0; if (nr > K5_RPW) nr = K5_RPW;
        #pragma unroll
        for (int r = 0; r < K5_RPW; r++) {
            int row = row0 + (r < nr ? r : 0);
            xw4[r * 32 + lane] = g_aggX[(long)row * 32 + lane];
        }
        __syncwarp();

        unsigned long long a01[K5_RPW], a23[K5_RPW];
        #pragma unroll
        for (int r = 0; r < K5_RPW; r++) { a01[r] = 0ULL; a23[r] = 0ULL; }

        #pragma unroll 2
        for (int kb = 0; kb < F; kb += 4) {
            ulonglong2 w0 = Wp[(kb + 0) * 32 + lane];   // LDS.128 x4
            ulonglong2 w1 = Wp[(kb + 1) * 32 + lane];
            ulonglong2 w2 = Wp[(kb + 2) * 32 + lane];
            ulonglong2 w3 = Wp[(kb + 3) * 32 + lane];
            #pragma unroll
            for (int r = 0; r < K5_RPW; r++) {
                float4 xv = xw4[r * 32 + (kb >> 2)];    // broadcast LDS.128
                unsigned long long x0, x1, x2, x3;
                PACK_F32X2(x0, xv.x, xv.x);             // ALU-pipe packs
                PACK_F32X2(x1, xv.y, xv.y);
                PACK_F32X2(x2, xv.z, xv.z);
                PACK_F32X2(x3, xv.w, xv.w);
                FMA_F32X2(a01[r], x0, w0.x, a01[r]);    // FMA pipe, 2 MACs ea
                FMA_F32X2(a23[r], x0, w0.y, a23[r]);
                FMA_F32X2(a01[r], x1, w1.x, a01[r]);
                FMA_F32X2(a23[r], x1, w1.y, a23[r]);
                FMA_F32X2(a01[r], x2, w2.x, a01[r]);
                FMA_F32X2(a23[r], x2, w2.y, a23[r]);
                FMA_F32X2(a01[r], x3, w3.x, a01[r]);
                FMA_F32X2(a23[r], x3, w3.y, a23[r]);
            }
        }

        float4 b4 = ((const float4*)bsum)[lane];
        for (int r = 0; r < nr; r++) {
            int row = row0 + r;
            float deg = (float)(g_rowend[row] - g_rowptr[row]);
            float4 o;
            UNPACK_F32X2(o.x, o.y, a01[r]);
            UNPACK_F32X2(o.z, o.w, a23[r]);
            o.x = fmaf(deg, b4.x, o.x);
            o.y = fmaf(deg, b4.y, o.y);
            o.z = fmaf(deg, b4.z, o.z);
            o.w = fmaf(deg, b4.w, o.w);
            #pragma unroll
            for (int k = 0; k < EFD; k++) {
                float ek = g_aggE[row * EFD + k];
                float4 w4 = ((const float4*)(Wes + (k << 7)))[lane];
                o.x = fmaf(ek, w4.x, o.x);
                o.y = fmaf(ek, w4.y, o.y);
                o.z = fmaf(ek, w4.z, o.z);
                o.w = fmaf(ek, w4.w, o.w);
            }
            o.x = fmaxf(o.x, 0.f); o.y = fmaxf(o.y, 0.f);
            o.z = fmaxf(o.z, 0.f); o.w = fmaxf(o.w, 0.f);
            ((float4*)out)[(long)row * 32 + lane] = o;
        }
        __syncwarp();
    }
}

// ---------------------------------------------------------------------------
extern "C" void kernel_launch(void* const* d_in, const int* in_sizes, int n_in,
                              void* d_out, int out_size) {
    const float* X  = (const float*)d_in[0];
    const void*  EI = d_in[1];
    const float* EF = (const float*)d_in[2];
    const float* W  = (const float*)d_in[3];
    const float* b  = (const float*)d_in[4];
    const float* We = (const float*)d_in[5];
    const float* be = (const float*)d_in[6];
    float* out = (float*)d_out;

    int N = in_sizes[0] / F;
    int E = in_sizes[2] / EFD;
    int B = (N + SCAN_T - 1) / SCAN_T;

    cudaFuncSetAttribute(k5_final, cudaFuncAttributeMaxDynamicSharedMemorySize,
                         K5_SMEM);

    k1_decode_hist<<<(E + 255) / 256, 256>>>(EI, N, E);
    k2_scan<<<B, SCAN_T>>>(N);
    k3_scatter<<<(E + 2047) / 2048, 256>>>(E);
    k4_aggregate<<<(N * 32 + 255) / 256, 256>>>((const float4*)X, EF, N);
    k5_final<<<148, K5_THREADS, K5_SMEM>>>((const float4*)W, b, We, be,
                                           out, N);
}